// round 7
// baseline (speedup 1.0000x reference)
#include <cuda_runtime.h>
#include <cuda_bf16.h>
#include <cstdint>

#define NROWS 4096
#define DIM   512
#define NCLS  100000
#define NBM   32
#define NBN   391            // ceil(100000/256)
#define NTILES (NBM * NBN)   // 12512
#define GRID  148
#define S_SCALE 30.0f
#define MARGIN  0.4f
#define XSI 127.0f           // int8 scale for xn
#define WSI 1000.0f          // int8 scale for W  (clips at |W|>0.127 = 6.3 sigma)
#define EXPS_I (S_SCALE / (XSI * WSI))   // exp arg multiplier on s32 acc

// ---------------- scratch (module-static device memory: allowed) ------------
__device__ __align__(128) uint8_t g_WB8[(size_t)NCLS * DIM];   // s8 W*1000
__device__ __align__(128) uint8_t g_xn8[(size_t)NROWS * DIM];  // s8 xn*127
__device__ float g_rowsum[NROWS];
__device__ float g_target[NROWS];

// ---------------- PTX helpers (sm_80-era, safe on sm_103) --------------------
__device__ __forceinline__ uint32_t smem_u32(const void* p) {
    uint32_t a;
    asm("{ .reg .u64 t; cvta.to.shared.u64 t, %1; cvt.u32.u64 %0, t; }" : "=r"(a) : "l"(p));
    return a;
}
#define CP_ASYNC16(dst, src) \
    asm volatile("cp.async.cg.shared.global [%0], [%1], 16;" :: "r"(dst), "l"(src) : "memory")
#define CP_COMMIT()  asm volatile("cp.async.commit_group;" ::: "memory")
#define CP_WAIT0()   asm volatile("cp.async.wait_group 0;" ::: "memory")
#define CP_WAIT1()   asm volatile("cp.async.wait_group 1;" ::: "memory")

__device__ __forceinline__ void ldsm4(uint32_t* r, uint32_t addr) {
    asm volatile("ldmatrix.sync.aligned.m8n8.x4.shared.b16 {%0,%1,%2,%3}, [%4];"
                 : "=r"(r[0]), "=r"(r[1]), "=r"(r[2]), "=r"(r[3]) : "r"(addr));
}
// s8 IMMA: m16n8k32, s32 accum.  Fragment bytes isomorphic to e4m3 k32.
__device__ __forceinline__ void mma_s8(int* c, const uint32_t* a,
                                       uint32_t b0, uint32_t b1) {
    asm volatile("mma.sync.aligned.m16n8k32.row.col.s32.s8.s8.s32 "
                 "{%0,%1,%2,%3}, {%4,%5,%6,%7}, {%8,%9}, {%0,%1,%2,%3};"
                 : "+r"(c[0]), "+r"(c[1]), "+r"(c[2]), "+r"(c[3])
                 : "r"(a[0]), "r"(a[1]), "r"(a[2]), "r"(a[3]), "r"(b0), "r"(b1));
}
__device__ __forceinline__ int q_s8(float v) {
    int a = __float2int_rn(v);
    return max(-127, min(127, a));
}
__device__ __forceinline__ uint32_t pack4_s8(float a0, float a1, float a2, float a3) {
    return (uint32_t)(q_s8(a0) & 0xff) | ((uint32_t)(q_s8(a1) & 0xff) << 8) |
           ((uint32_t)(q_s8(a2) & 0xff) << 16) | ((uint32_t)(q_s8(a3) & 0xff) << 24);
}

// ---------------- tiling (all pitches in BYTES) -------------------------------
#define BM 128
#define BN 256
#define CHUNK_B 128          // bytes of K per pipeline chunk
#define NCHUNK  4            // DIM / CHUNK_B
#define APITCH 528           // 132 words == 4 mod 32 (ldsm conflict-free)
#define BPITCH 144           // 36 words  == 4 mod 32

#define A_BYTES       (BM * APITCH)                  // 67584
#define B_STAGE_BYTES (BN * BPITCH)                  // 36864
#define B_OFF         A_BYTES
#define SMEM_BYTES    (B_OFF + 2 * B_STAGE_BYTES)    // 141312

// ======================= kernel 1: prep (fused convert + normalize) ==========
__device__ __forceinline__ float block_reduce_128(float v, float* sbuf, int tid) {
    #pragma unroll
    for (int o = 16; o > 0; o >>= 1) v += __shfl_xor_sync(0xffffffffu, v, o);
    if ((tid & 31) == 0) sbuf[tid >> 5] = v;
    __syncthreads();
    float r = sbuf[0] + sbuf[1] + sbuf[2] + sbuf[3];
    __syncthreads();
    return r;
}

__global__ void prep_kernel(const float* __restrict__ x,
                            const int* __restrict__ labels_raw,
                            const float* __restrict__ W) {
    __shared__ float sbuf[4];
    const int tid = threadIdx.x;
    if (blockIdx.x < NROWS) {
        const int row = blockIdx.x;
        const float* xr = x + (size_t)row * DIM;
        float v[4]; float ss = 0.f;
        #pragma unroll
        for (int j = 0; j < 4; j++) { v[j] = xr[tid + 128*j]; ss += v[j]*v[j]; }
        ss = block_reduce_128(ss, sbuf, tid);
        float inv = rsqrtf(ss);
        #pragma unroll
        for (int j = 0; j < 4; j++)
            g_xn8[(size_t)row * DIM + tid + 128*j] =
                (uint8_t)(q_s8(v[j] * inv * XSI) & 0xff);

        bool is64 = (labels_raw[1] == 0 && labels_raw[3] == 0 &&
                     labels_raw[5] == 0 && labels_raw[7] == 0);
        int lab = is64 ? labels_raw[2*row] : labels_raw[row];
        const float* w = W + (size_t)lab * DIM;
        float dot = 0.f;
        #pragma unroll
        for (int j = 0; j < 4; j++) dot += v[j] * w[tid + 128*j];
        dot = block_reduce_128(dot, sbuf, tid);
        if (tid == 0) { g_target[row] = dot * inv; g_rowsum[row] = 0.f; }
    } else {
        const size_t base = ((size_t)(blockIdx.x - NROWS) * 128 + tid) * 16;
        const float4* src = reinterpret_cast<const float4*>(W + base);
        float4 v0 = src[0], v1 = src[1], v2 = src[2], v3 = src[3];
        uint4 o;
        o.x = pack4_s8(v0.x*WSI, v0.y*WSI, v0.z*WSI, v0.w*WSI);
        o.y = pack4_s8(v1.x*WSI, v1.y*WSI, v1.z*WSI, v1.w*WSI);
        o.z = pack4_s8(v2.x*WSI, v2.y*WSI, v2.z*WSI, v2.w*WSI);
        o.w = pack4_s8(v3.x*WSI, v3.y*WSI, v3.z*WSI, v3.w*WSI);
        *reinterpret_cast<uint4*>(g_WB8 + base) = o;
    }
}

// ======================= kernel 2: s8-IMMA GEMM + exp rowsum =================
__device__ __forceinline__ void issue_b_chunk(uint32_t bs_dst, int bn, int k0, int tid) {
    #pragma unroll
    for (int i = 0; i < 8; i++) {
        int v = tid + 256 * i;                  // 2048 vectors = 256 rows x 8
        int r = v >> 3, kv = v & 7;
        int grow = bn * BN + r; if (grow >= NCLS) grow = NCLS - 1;
        const void* src = g_WB8 + ((size_t)grow * DIM + k0 + kv * 16);
        CP_ASYNC16(bs_dst + r * BPITCH + kv * 16, src);
    }
}

__global__ void __launch_bounds__(256, 1) gemm_exp_kernel() {
    extern __shared__ __align__(16) char smem[];
    const uint32_t sb = smem_u32(smem);
    const int tid = threadIdx.x, wid = tid >> 5, lane = tid & 31;
    const int wm = wid & 1, wn = wid >> 1;
    const int cta = blockIdx.x;
    const int t0 = (cta * NTILES) / GRID;
    const int t1 = ((cta + 1) * NTILES) / GRID;

    const int lrow = lane & 15, lk16 = (lane >> 4) * 16;
    const uint32_t a_lane = sb + (wm * 64 + lrow) * APITCH + lk16;
    const uint32_t b_lane = sb + B_OFF + (wn * 64 + lrow) * BPITCH + lk16;

    int t = t0;
    while (t < t1) {
        const int bm = t / NBN;
        const int bn0 = t - bm * NBN;
        const int seg_end = min(t1, (bm + 1) * NBN);
        const int total = (seg_end - t) * NCHUNK;

        __syncthreads();   // prior-segment readers done before overwriting SMEM
        const uint8_t* xa = g_xn8 + (size_t)bm * BM * DIM;
        #pragma unroll 4
        for (int i = 0; i < 16; i++) {
            int v = tid + 256 * i;              // 4096 vectors = 128 rows x 32
            int r = v >> 5, kv = v & 31;
            CP_ASYNC16(sb + r * APITCH + kv * 16, xa + ((size_t)r * DIM + kv * 16));
        }
        CP_COMMIT();
        issue_b_chunk(sb + B_OFF, bn0, 0, tid);
        CP_COMMIT();

        int acc[4][8][4];
        #pragma unroll
        for (int fm = 0; fm < 4; fm++)
            #pragma unroll
            for (int q = 0; q < 8; q++)
                #pragma unroll
                for (int e = 0; e < 4; e++) acc[fm][q][e] = 0;
        float rsum[8] = {0.f,0.f,0.f,0.f,0.f,0.f,0.f,0.f};

        for (int j = 0; j < total; j++) {
            __syncthreads();
            int jn = j + 1;
            if (jn < total) {
                issue_b_chunk(sb + B_OFF + (jn & 1) * B_STAGE_BYTES,
                              bn0 + (jn >> 2), (jn & 3) * CHUNK_B, tid);
                CP_COMMIT();
                CP_WAIT1();
            } else {
                CP_WAIT0();
            }
            __syncthreads();

            const uint32_t bch = b_lane + (j & 1) * B_STAGE_BYTES;
            const uint32_t ach = a_lane + (j & 3) * CHUNK_B;
            #pragma unroll
            for (int ks = 0; ks < 4; ks++) {      // 4 x k32 per 128B chunk
                uint32_t Af[4][4], Bf[4][4];
                #pragma unroll
                for (int fm = 0; fm < 4; fm++)
                    ldsm4(Af[fm], ach + fm * 16 * APITCH + ks * 32);
                #pragma unroll
                for (int f = 0; f < 4; f++)
                    ldsm4(Bf[f], bch + f * 16 * BPITCH + ks * 32);
                #pragma unroll
                for (int fm = 0; fm < 4; fm++)
                    #pragma unroll
                    for (int f = 0; f < 4; f++) {
                        mma_s8(acc[fm][2*f],   Af[fm], Bf[f][0], Bf[f][2]);
                        mma_s8(acc[fm][2*f+1], Af[fm], Bf[f][1], Bf[f][3]);
                    }
            }

            // ---- per-tile epilogue: exp on accumulator registers ----
            if ((j & 3) == 3) {
                const int bn = bn0 + (j >> 2);
                if (bn != NBN - 1) {
                    #pragma unroll
                    for (int fm = 0; fm < 4; fm++) {
                        float s0 = 0.f, s1 = 0.f;
                        #pragma unroll
                        for (int q = 0; q < 8; q++) {
                            s0 += __expf(EXPS_I * (float)acc[fm][q][0]);
                            s0 += __expf(EXPS_I * (float)acc[fm][q][1]);
                            s1 += __expf(EXPS_I * (float)acc[fm][q][2]);
                            s1 += __expf(EXPS_I * (float)acc[fm][q][3]);
                            acc[fm][q][0] = 0; acc[fm][q][1] = 0;
                            acc[fm][q][2] = 0; acc[fm][q][3] = 0;
                        }
                        rsum[2*fm] += s0; rsum[2*fm+1] += s1;
                    }
                } else {
                    // tail tile: cols [99840, 100096), valid local col < 160
                    const int cb = wn * 64 + (lane & 3) * 2;
                    #pragma unroll
                    for (int fm = 0; fm < 4; fm++) {
                        float s0 = 0.f, s1 = 0.f;
                        #pragma unroll
                        for (int q = 0; q < 8; q++) {
                            int c0 = cb + q * 8;
                            if (c0 < 160) {
                                s0 += __expf(EXPS_I * (float)acc[fm][q][0]);
                                s1 += __expf(EXPS_I * (float)acc[fm][q][2]);
                            }
                            if (c0 + 1 < 160) {
                                s0 += __expf(EXPS_I * (float)acc[fm][q][1]);
                                s1 += __expf(EXPS_I * (float)acc[fm][q][3]);
                            }
                            acc[fm][q][0] = 0; acc[fm][q][1] = 0;
                            acc[fm][q][2] = 0; acc[fm][q][3] = 0;
                        }
                        rsum[2*fm] += s0; rsum[2*fm+1] += s1;
                    }
                }
            }
        }

        // ---- segment flush: quad-reduce, one atomic per row ----
        #pragma unroll
        for (int k = 0; k < 8; k++) {
            float v = rsum[k];
            v += __shfl_xor_sync(0xffffffffu, v, 1);
            v += __shfl_xor_sync(0xffffffffu, v, 2);
            if ((lane & 3) == 0) {
                int row = bm * BM + wm * 64 + (k >> 1) * 16 + (lane >> 2) + (k & 1) * 8;
                atomicAdd(&g_rowsum[row], v);
            }
        }
        t = seg_end;
    }
}

// ======================= kernel 3: finalize ===================================
__global__ void finalize_kernel(float* __restrict__ out) {
    __shared__ double sd[512];
    int tid = threadIdx.x;
    double local = 0.0;
    for (int i = tid; i < NROWS; i += 512) {
        float t   = g_target[i];
        float num = S_SCALE * (t - MARGIN);
        float denom = __expf(num) + g_rowsum[i] - __expf(S_SCALE * t);
        local += (double)num - (double)__logf(denom);
    }
    sd[tid] = local;
    __syncthreads();
    for (int s = 256; s > 0; s >>= 1) {
        if (tid < s) sd[tid] += sd[tid + s];
        __syncthreads();
    }
    if (tid == 0) out[0] = (float)(-sd[0] / (double)NROWS);
}

// ======================= launch ==============================================
extern "C" void kernel_launch(void* const* d_in, const int* in_sizes, int n_in,
                              void* d_out, int out_size) {
    const float* x      = (const float*)d_in[0];
    const int*   labels = (const int*)d_in[1];
    const float* W      = (const float*)d_in[2];
    float* out = (float*)d_out;

    cudaFuncSetAttribute(gemm_exp_kernel,
                         cudaFuncAttributeMaxDynamicSharedMemorySize, SMEM_BYTES);

    prep_kernel<<<NROWS + 25000, 128>>>(x, labels, W);
    gemm_exp_kernel<<<GRID, 256, SMEM_BYTES>>>();
    finalize_kernel<<<1, 512>>>(out);
}

// round 8
// speedup vs baseline: 2.6004x; 2.6004x over previous
#include <cuda_runtime.h>
#include <cuda_bf16.h>
#include <cuda_fp16.h>
#include <cuda_fp8.h>
#include <cstdint>

#define NROWS 4096
#define DIM   512
#define NCLS  100000
#define NBM   32
#define NBN   391            // ceil(100000/256)
#define NTILES (NBM * NBN)   // 12512
#define GRID  148
#define S_SCALE 30.0f
#define MARGIN  0.4f
#define XS 8.0f              // fp8 scale for xn
#define WS 32.0f             // fp8 scale for W
#define EXPS (S_SCALE / (XS * WS))   // exp arg multiplier on raw acc

// ---------------- scratch (module-static device memory: allowed) ------------
__device__ __align__(128) uint8_t g_WB8[(size_t)NCLS * DIM];   // e4m3 W*32
__device__ __align__(128) uint8_t g_xn8[(size_t)NROWS * DIM];  // e4m3 xn*8
__device__ float g_rowsum[NROWS];
__device__ float g_target[NROWS];

// ---------------- PTX helpers (sm_80/89-era, safe on sm_103) ----------------
__device__ __forceinline__ uint32_t smem_u32(const void* p) {
    uint32_t a;
    asm("{ .reg .u64 t; cvta.to.shared.u64 t, %1; cvt.u32.u64 %0, t; }" : "=r"(a) : "l"(p));
    return a;
}
#define CP_ASYNC16(dst, src) \
    asm volatile("cp.async.cg.shared.global [%0], [%1], 16;" :: "r"(dst), "l"(src) : "memory")
#define CP_COMMIT()  asm volatile("cp.async.commit_group;" ::: "memory")
#define CP_WAIT0()   asm volatile("cp.async.wait_group 0;" ::: "memory")
#define CP_WAIT1()   asm volatile("cp.async.wait_group 1;" ::: "memory")

__device__ __forceinline__ void ldsm4(uint32_t* r, uint32_t addr) {
    asm volatile("ldmatrix.sync.aligned.m8n8.x4.shared.b16 {%0,%1,%2,%3}, [%4];"
                 : "=r"(r[0]), "=r"(r[1]), "=r"(r[2]), "=r"(r[3]) : "r"(addr));
}
// e4m3 MMA with **f16 accumulator**: m16n8k32, D/C = 2 x .f16x2 regs.
__device__ __forceinline__ void mma_fp8_h(uint32_t* c, const uint32_t* a,
                                          uint32_t b0, uint32_t b1) {
    asm volatile("mma.sync.aligned.m16n8k32.row.col.f16.e4m3.e4m3.f16 "
                 "{%0,%1}, {%2,%3,%4,%5}, {%6,%7}, {%0,%1};"
                 : "+r"(c[0]), "+r"(c[1])
                 : "r"(a[0]), "r"(a[1]), "r"(a[2]), "r"(a[3]), "r"(b0), "r"(b1));
}
__device__ __forceinline__ uint32_t pack4_e4m3(float a0, float a1, float a2, float a3) {
    __nv_fp8x2_e4m3 lo(make_float2(a0, a1));
    __nv_fp8x2_e4m3 hi(make_float2(a2, a3));
    return (uint32_t)lo.__x | ((uint32_t)hi.__x << 16);
}

// ---------------- tiling (all pitches in BYTES) -------------------------------
#define BM 128
#define BN 256
#define CHUNK_B 128          // bytes of K per pipeline chunk (= 128 fp8 elems)
#define NCHUNK  4            // DIM / CHUNK_B
#define APITCH 528           // 132 words == 4 mod 32 (ldsm conflict-free)
#define BPITCH 144           // 36 words  == 4 mod 32

#define A_BYTES       (BM * APITCH)                  // 67584
#define B_STAGE_BYTES (BN * BPITCH)                  // 36864
#define B_OFF         A_BYTES
#define SMEM_BYTES    (B_OFF + 2 * B_STAGE_BYTES)    // 141312

// ======================= kernel 1: prep (fused convert + normalize) ==========
__device__ __forceinline__ float block_reduce_128(float v, float* sbuf, int tid) {
    #pragma unroll
    for (int o = 16; o > 0; o >>= 1) v += __shfl_xor_sync(0xffffffffu, v, o);
    if ((tid & 31) == 0) sbuf[tid >> 5] = v;
    __syncthreads();
    float r = sbuf[0] + sbuf[1] + sbuf[2] + sbuf[3];
    __syncthreads();
    return r;
}

__global__ void prep_kernel(const float* __restrict__ x,
                            const int* __restrict__ labels_raw,
                            const float* __restrict__ W) {
    __shared__ float sbuf[4];
    const int tid = threadIdx.x;
    if (blockIdx.x < NROWS) {
        const int row = blockIdx.x;
        const float* xr = x + (size_t)row * DIM;
        float v[4]; float ss = 0.f;
        #pragma unroll
        for (int j = 0; j < 4; j++) { v[j] = xr[tid + 128*j]; ss += v[j]*v[j]; }
        ss = block_reduce_128(ss, sbuf, tid);
        float inv = rsqrtf(ss);
        #pragma unroll
        for (int j = 0; j < 4; j++)
            g_xn8[(size_t)row * DIM + tid + 128*j] =
                __nv_fp8_e4m3(v[j] * inv * XS).__x;

        bool is64 = (labels_raw[1] == 0 && labels_raw[3] == 0 &&
                     labels_raw[5] == 0 && labels_raw[7] == 0);
        int lab = is64 ? labels_raw[2*row] : labels_raw[row];
        const float* w = W + (size_t)lab * DIM;
        float dot = 0.f;
        #pragma unroll
        for (int j = 0; j < 4; j++) dot += v[j] * w[tid + 128*j];
        dot = block_reduce_128(dot, sbuf, tid);
        if (tid == 0) { g_target[row] = dot * inv; g_rowsum[row] = 0.f; }
    } else {
        const size_t base = ((size_t)(blockIdx.x - NROWS) * 128 + tid) * 16;
        const float4* src = reinterpret_cast<const float4*>(W + base);
        float4 v0 = src[0], v1 = src[1], v2 = src[2], v3 = src[3];
        uint4 o;
        o.x = pack4_e4m3(v0.x*WS, v0.y*WS, v0.z*WS, v0.w*WS);
        o.y = pack4_e4m3(v1.x*WS, v1.y*WS, v1.z*WS, v1.w*WS);
        o.z = pack4_e4m3(v2.x*WS, v2.y*WS, v2.z*WS, v2.w*WS);
        o.w = pack4_e4m3(v3.x*WS, v3.y*WS, v3.z*WS, v3.w*WS);
        *reinterpret_cast<uint4*>(g_WB8 + base) = o;
    }
}

// ======================= kernel 2: fp8-mma (f16 acc) GEMM + exp rowsum =======
__device__ __forceinline__ void issue_b_chunk(uint32_t bs_dst, int bn, int k0, int tid) {
    #pragma unroll
    for (int i = 0; i < 8; i++) {
        int v = tid + 256 * i;                  // 2048 vectors = 256 rows x 8
        int r = v >> 3, kv = v & 7;
        int grow = bn * BN + r; if (grow >= NCLS) grow = NCLS - 1;
        const void* src = g_WB8 + ((size_t)grow * DIM + k0 + kv * 16);
        CP_ASYNC16(bs_dst + r * BPITCH + kv * 16, src);
    }
}

__device__ __forceinline__ float2 h2f2(uint32_t r) {
    return __half22float2(*reinterpret_cast<__half2*>(&r));
}

__global__ void __launch_bounds__(256, 1) gemm_exp_kernel() {
    extern __shared__ __align__(16) char smem[];
    const uint32_t sb = smem_u32(smem);
    const int tid = threadIdx.x, wid = tid >> 5, lane = tid & 31;
    const int wm = wid & 1, wn = wid >> 1;
    const int cta = blockIdx.x;
    const int t0 = (cta * NTILES) / GRID;
    const int t1 = ((cta + 1) * NTILES) / GRID;

    const int lrow = lane & 15, lk16 = (lane >> 4) * 16;
    const uint32_t a_lane = sb + (wm * 64 + lrow) * APITCH + lk16;
    const uint32_t b_lane = sb + B_OFF + (wn * 64 + lrow) * BPITCH + lk16;

    int t = t0;
    while (t < t1) {
        const int bm = t / NBN;
        const int bn0 = t - bm * NBN;
        const int seg_end = min(t1, (bm + 1) * NBN);
        const int total = (seg_end - t) * NCHUNK;

        __syncthreads();   // prior-segment readers done before overwriting SMEM
        const uint8_t* xa = g_xn8 + (size_t)bm * BM * DIM;
        #pragma unroll 4
        for (int i = 0; i < 16; i++) {
            int v = tid + 256 * i;              // 4096 vectors = 128 rows x 32
            int r = v >> 5, kv = v & 31;
            CP_ASYNC16(sb + r * APITCH + kv * 16, xa + ((size_t)r * DIM + kv * 16));
        }
        CP_COMMIT();
        issue_b_chunk(sb + B_OFF, bn0, 0, tid);
        CP_COMMIT();

        // f16x2 accumulators: [fm][q][0]=rows r, cols {2c,2c+1}; [1]=rows r+8
        uint32_t acc[4][8][2];
        #pragma unroll
        for (int fm = 0; fm < 4; fm++)
            #pragma unroll
            for (int q = 0; q < 8; q++) { acc[fm][q][0] = 0u; acc[fm][q][1] = 0u; }
        float rsum[8] = {0.f,0.f,0.f,0.f,0.f,0.f,0.f,0.f};

        for (int j = 0; j < total; j++) {
            __syncthreads();
            int jn = j + 1;
            if (jn < total) {
                issue_b_chunk(sb + B_OFF + (jn & 1) * B_STAGE_BYTES,
                              bn0 + (jn >> 2), (jn & 3) * CHUNK_B, tid);
                CP_COMMIT();
                CP_WAIT1();
            } else {
                CP_WAIT0();
            }
            __syncthreads();

            const uint32_t bch = b_lane + (j & 1) * B_STAGE_BYTES;
            const uint32_t ach = a_lane + (j & 3) * CHUNK_B;
            #pragma unroll
            for (int ks = 0; ks < 4; ks++) {      // 4 x k32 per 128B chunk
                uint32_t Af[4][4], Bf[4][4];
                #pragma unroll
                for (int fm = 0; fm < 4; fm++)
                    ldsm4(Af[fm], ach + fm * 16 * APITCH + ks * 32);
                #pragma unroll
                for (int f = 0; f < 4; f++)
                    ldsm4(Bf[f], bch + f * 16 * BPITCH + ks * 32);
                #pragma unroll
                for (int fm = 0; fm < 4; fm++)
                    #pragma unroll
                    for (int f = 0; f < 4; f++) {
                        mma_fp8_h(acc[fm][2*f],   Af[fm], Bf[f][0], Bf[f][2]);
                        mma_fp8_h(acc[fm][2*f+1], Af[fm], Bf[f][1], Bf[f][3]);
                    }
            }

            // ---- per-tile epilogue: unpack f16x2, exp, accumulate rowsums ----
            if ((j & 3) == 3) {
                const int bn = bn0 + (j >> 2);
                if (bn != NBN - 1) {
                    #pragma unroll
                    for (int fm = 0; fm < 4; fm++) {
                        float s0 = 0.f, s1 = 0.f;
                        #pragma unroll
                        for (int q = 0; q < 8; q++) {
                            float2 f0 = h2f2(acc[fm][q][0]);
                            float2 f1 = h2f2(acc[fm][q][1]);
                            s0 += __expf(EXPS * f0.x) + __expf(EXPS * f0.y);
                            s1 += __expf(EXPS * f1.x) + __expf(EXPS * f1.y);
                            acc[fm][q][0] = 0u; acc[fm][q][1] = 0u;
                        }
                        rsum[2*fm] += s0; rsum[2*fm+1] += s1;
                    }
                } else {
                    // tail tile: cols [99840, 100096), valid local col < 160
                    const int cb = wn * 64 + (lane & 3) * 2;
                    #pragma unroll
                    for (int fm = 0; fm < 4; fm++) {
                        float s0 = 0.f, s1 = 0.f;
                        #pragma unroll
                        for (int q = 0; q < 8; q++) {
                            int c0 = cb + q * 8;
                            float2 f0 = h2f2(acc[fm][q][0]);
                            float2 f1 = h2f2(acc[fm][q][1]);
                            if (c0 < 160) {
                                s0 += __expf(EXPS * f0.x);
                                s1 += __expf(EXPS * f1.x);
                            }
                            if (c0 + 1 < 160) {
                                s0 += __expf(EXPS * f0.y);
                                s1 += __expf(EXPS * f1.y);
                            }
                            acc[fm][q][0] = 0u; acc[fm][q][1] = 0u;
                        }
                        rsum[2*fm] += s0; rsum[2*fm+1] += s1;
                    }
                }
            }
        }

        // ---- segment flush: quad-reduce, one atomic per row ----
        #pragma unroll
        for (int k = 0; k < 8; k++) {
            float v = rsum[k];
            v += __shfl_xor_sync(0xffffffffu, v, 1);
            v += __shfl_xor_sync(0xffffffffu, v, 2);
            if ((lane & 3) == 0) {
                int row = bm * BM + wm * 64 + (k >> 1) * 16 + (lane >> 2) + (k & 1) * 8;
                atomicAdd(&g_rowsum[row], v);
            }
        }
        t = seg_end;
    }
}

// ======================= kernel 3: finalize ===================================
__global__ void finalize_kernel(float* __restrict__ out) {
    __shared__ double sd[512];
    int tid = threadIdx.x;
    double local = 0.0;
    for (int i = tid; i < NROWS; i += 512) {
        float t   = g_target[i];
        float num = S_SCALE * (t - MARGIN);
        float denom = __expf(num) + g_rowsum[i] - __expf(S_SCALE * t);
        local += (double)num - (double)__logf(denom);
    }
    sd[tid] = local;
    __syncthreads();
    for (int s = 256; s > 0; s >>= 1) {
        if (tid < s) sd[tid] += sd[tid + s];
        __syncthreads();
    }
    if (tid == 0) out[0] = (float)(-sd[0] / (double)NROWS);
}

// ======================= launch ==============================================
extern "C" void kernel_launch(void* const* d_in, const int* in_sizes, int n_in,
                              void* d_out, int out_size) {
    const float* x      = (const float*)d_in[0];
    const int*   labels = (const int*)d_in[1];
    const float* W      = (const float*)d_in[2];
    float* out = (float*)d_out;

    cudaFuncSetAttribute(gemm_exp_kernel,
                         cudaFuncAttributeMaxDynamicSharedMemorySize, SMEM_BYTES);

    prep_kernel<<<NROWS + 25000, 128>>>(x, labels, W);
    gemm_exp_kernel<<<GRID, 256, SMEM_BYTES>>>();
    finalize_kernel<<<1, 512>>>(out);
}